// round 12
// baseline (speedup 1.0000x reference)
#include <cuda_runtime.h>
#include <cuda_bf16.h>
#include <cstdint>
#include <cstddef>

#define T_SEQ   256
#define BATCH   64
#define DIN     200
#define HIDN    300
#define NLAYERS 8
#define G5      1500
#define G6      1800
#define NPAD    1920
#define TBROWS  (T_SEQ*BATCH)           // 16384
#define OUT_SZ  (BATCH*T_SEQ*HIDN)
#define LAYER_SZ (T_SEQ*BATCH*HIDN)
#define KPAD_MAX 320

// scan partitioning: 4 batch-groups x 13 column-CTAs x 24 j-cols
#define NGRP    4
#define GB      16                      // batches per group
#define NCOL    13                      // CTAs per group
#define JPC     24                      // j-columns per CTA
#define SCANT   512                     // threads per scan CTA
#define SHK     320                     // padded K for scan MMA (20 k-steps)
#define SHP     328                     // smem pitch halves (656B)
#define ZP      137                     // z smem pitch (floats)

// ---- scratch (device globals; no runtime allocation allowed) ----
__device__ float         g_pi[(size_t)NPAD * TBROWS];   // TRANSPOSED: [col][t*64+b]
__device__ __nv_bfloat16 g_Ah[(size_t)TBROWS * KPAD_MAX];
__device__ __nv_bfloat16 g_Al[(size_t)TBROWS * KPAD_MAX];
__device__ __nv_bfloat16 g_Wh[(size_t)NPAD * KPAD_MAX];
__device__ __nv_bfloat16 g_Wl[(size_t)NPAD * KPAD_MAX];
__device__ __nv_bfloat16 g_hhi[NGRP * 2 * GB * SHK];    // [grp][p][b][k]
__device__ __nv_bfloat16 g_hlo[NGRP * 2 * GB * SHK];
__device__ int           g_flag[NLAYERS * NGRP * 32];   // per-CTA step flags

// ============================ PTX helpers ============================
__device__ __forceinline__ uint32_t smem_u32(const void* p) {
    uint32_t a;
    asm("{ .reg .u64 t; cvta.to.shared.u64 t, %1; cvt.u32.u64 %0, t; }"
        : "=r"(a) : "l"(p));
    return a;
}
__device__ __forceinline__ void cp16(uint32_t dst, const void* src) {
    asm volatile("cp.async.cg.shared.global [%0], [%1], 16;"
                 :: "r"(dst), "l"(src) : "memory");
}
__device__ __forceinline__ void cp_commit() {
    asm volatile("cp.async.commit_group;" ::: "memory");
}
template <int N>
__device__ __forceinline__ void cp_wait() {
    asm volatile("cp.async.wait_group %0;" :: "n"(N) : "memory");
}
__device__ __forceinline__ void ldsm4(uint32_t* r, uint32_t addr) {
    asm volatile("ldmatrix.sync.aligned.m8n8.x4.shared.b16 {%0,%1,%2,%3}, [%4];"
                 : "=r"(r[0]), "=r"(r[1]), "=r"(r[2]), "=r"(r[3]) : "r"(addr));
}
__device__ __forceinline__ void mma_bf16(float* c, const uint32_t* a, const uint32_t* b) {
    asm volatile(
        "mma.sync.aligned.m16n8k16.row.col.f32.bf16.bf16.f32 "
        "{%0,%1,%2,%3}, {%4,%5,%6,%7}, {%8,%9}, {%0,%1,%2,%3};"
        : "+f"(c[0]), "+f"(c[1]), "+f"(c[2]), "+f"(c[3])
        : "r"(a[0]), "r"(a[1]), "r"(a[2]), "r"(a[3]), "r"(b[0]), "r"(b[1]));
}

// ========================= conversion kernels =========================
__global__ void __launch_bounds__(256) conv_A(
    const float* __restrict__ src, __nv_bfloat16* __restrict__ hi,
    __nv_bfloat16* __restrict__ lo, int K, int Kpad, int l0)
{
    int warp = (blockIdx.x * 256 + threadIdx.x) >> 5;
    int lane = threadIdx.x & 31;
    if (warp >= TBROWS) return;
    const float* s;
    if (l0) { int b = warp & 63, t = warp >> 6; s = src + ((size_t)b * T_SEQ + t) * DIN; }
    else    { s = src + (size_t)warp * HIDN; }
    size_t o = (size_t)warp * Kpad;
    for (int k = lane; k < Kpad; k += 32) {
        float x = (k < K) ? s[k] : 0.f;
        __nv_bfloat16 h = __float2bfloat16(x);
        hi[o + k] = h;
        lo[o + k] = __float2bfloat16(x - __bfloat162float(h));
    }
}

// W [K][1800] -> transposed bf16 hi/lo [NPAD][Kpad]
__global__ void __launch_bounds__(256) conv_W(
    const float* __restrict__ W, __nv_bfloat16* __restrict__ hi,
    __nv_bfloat16* __restrict__ lo, int K, int Kpad)
{
    __shared__ float t[32][33];
    int k0 = blockIdx.x * 32, n0 = blockIdx.y * 32;
    int tx = threadIdx.x & 31, ty = threadIdx.x >> 5;
    #pragma unroll
    for (int i = 0; i < 4; i++) {
        int ky = k0 + ty + i * 8, n = n0 + tx;
        float v = 0.f;
        if (ky < K && n < G6) v = W[(size_t)ky * G6 + n];
        t[ty + i * 8][tx] = v;
    }
    __syncthreads();
    #pragma unroll
    for (int i = 0; i < 4; i++) {
        int n = n0 + ty + i * 8, k = k0 + tx;
        if (n < NPAD && k < Kpad) {
            float v = t[tx][ty + i * 8];
            __nv_bfloat16 h = __float2bfloat16(v);
            hi[(size_t)n * Kpad + k] = h;
            lo[(size_t)n * Kpad + k] = __float2bfloat16(v - __bfloat162float(h));
        }
    }
}

// ===================== split-bf16 HMMA GEMM (input projections) =====================
#define KC 32
#define PITCH 40
#define TILE_H (128 * PITCH)
#define STAGE_H (4 * TILE_H)
#define SMEM_GEMM_BYTES (2 * STAGE_H * 2)

__global__ void __launch_bounds__(256) hgemm_tc(
    const __nv_bfloat16* __restrict__ Ah, const __nv_bfloat16* __restrict__ Al,
    const __nv_bfloat16* __restrict__ Bh, const __nv_bfloat16* __restrict__ Bl,
    float* __restrict__ pi, int Kpad, int nch)
{
    extern __shared__ __nv_bfloat16 sm[];
    const int tid = threadIdx.x, warp = tid >> 5, lane = tid & 31;
    const int bn = blockIdx.x * 128;
    const int bm = blockIdx.y * 128;
    const int wm = (warp >> 2) * 64;
    const int wn = (warp & 3) * 32;
    const uint32_t sb = smem_u32(sm);

    float acc[4][4][4];
    #pragma unroll
    for (int i = 0; i < 4; i++)
        #pragma unroll
        for (int j = 0; j < 4; j++)
            #pragma unroll
            for (int q = 0; q < 4; q++) acc[i][j][q] = 0.f;

    auto load_chunk = [&](int c, int s) {
        const int c0 = c * KC;
        const uint32_t sbase = sb + (uint32_t)s * STAGE_H * 2;
        #pragma unroll
        for (int it = 0; it < 8; it++) {
            int idx = it * 256 + tid;
            int tl  = idx >> 9;
            int r   = (idx >> 2) & 127;
            int seg = idx & 3;
            const __nv_bfloat16* src;
            if      (tl == 0) src = Ah + ((size_t)(bm + r) * Kpad + c0);
            else if (tl == 1) src = Al + ((size_t)(bm + r) * Kpad + c0);
            else if (tl == 2) src = Bh + ((size_t)(bn + r) * Kpad + c0);
            else              src = Bl + ((size_t)(bn + r) * Kpad + c0);
            uint32_t dst = sbase + (uint32_t)(tl * TILE_H + r * PITCH + seg * 8) * 2;
            cp16(dst, src + seg * 8);
        }
    };

    load_chunk(0, 0);
    cp_commit();

    for (int c = 0; c < nch; c++) {
        if (c + 1 < nch) { load_chunk(c + 1, (c + 1) & 1); cp_commit(); cp_wait<1>(); }
        else             { cp_wait<0>(); }
        __syncthreads();

        const uint32_t st = sb + (uint32_t)(c & 1) * STAGE_H * 2;
        const uint32_t sAh = st, sAl = st + TILE_H * 2;
        const uint32_t sBh = st + 2 * TILE_H * 2, sBl = st + 3 * TILE_H * 2;

        #pragma unroll
        for (int ks = 0; ks < 2; ks++) {
            const int k0 = ks * 16;
            uint32_t ah[4][4], al[4][4], bh[4][2], bl[4][2];
            {
                int arow = lane & 15, akc = k0 + (lane >> 4) * 8;
                #pragma unroll
                for (int mt = 0; mt < 4; mt++) {
                    uint32_t off = (uint32_t)((wm + mt * 16 + arow) * PITCH + akc) * 2;
                    ldsm4(ah[mt], sAh + off);
                    ldsm4(al[mt], sAl + off);
                }
            }
            {
                int g = lane >> 3;
                int brow = ((g >= 2) ? 8 : 0) + (lane & 7);
                int bkc  = k0 + ((g & 1) ? 8 : 0);
                #pragma unroll
                for (int h = 0; h < 2; h++) {
                    uint32_t off = (uint32_t)((wn + h * 16 + brow) * PITCH + bkc) * 2;
                    uint32_t r4[4];
                    ldsm4(r4, sBh + off);
                    bh[h * 2 + 0][0] = r4[0]; bh[h * 2 + 0][1] = r4[1];
                    bh[h * 2 + 1][0] = r4[2]; bh[h * 2 + 1][1] = r4[3];
                    ldsm4(r4, sBl + off);
                    bl[h * 2 + 0][0] = r4[0]; bl[h * 2 + 0][1] = r4[1];
                    bl[h * 2 + 1][0] = r4[2]; bl[h * 2 + 1][1] = r4[3];
                }
            }
            #pragma unroll
            for (int mt = 0; mt < 4; mt++)
                #pragma unroll
                for (int nt = 0; nt < 4; nt++)
                    mma_bf16(acc[mt][nt], ah[mt], bh[nt]);
            #pragma unroll
            for (int mt = 0; mt < 4; mt++)
                #pragma unroll
                for (int nt = 0; nt < 4; nt++)
                    mma_bf16(acc[mt][nt], ah[mt], bl[nt]);
            #pragma unroll
            for (int mt = 0; mt < 4; mt++)
                #pragma unroll
                for (int nt = 0; nt < 4; nt++)
                    mma_bf16(acc[mt][nt], al[mt], bh[nt]);
        }
        __syncthreads();
    }

    float* scS = (float*)sm;                 // 128 cols x pitch 129
    #pragma unroll
    for (int mt = 0; mt < 4; mt++) {
        int grow = wm + mt * 16 + (lane >> 2);
        #pragma unroll
        for (int nt = 0; nt < 4; nt++) {
            int gcol = wn + nt * 8 + (lane & 3) * 2;
            scS[(size_t)gcol * 129 + grow]           = acc[mt][nt][0];
            scS[(size_t)(gcol + 1) * 129 + grow]     = acc[mt][nt][1];
            scS[(size_t)gcol * 129 + grow + 8]       = acc[mt][nt][2];
            scS[(size_t)(gcol + 1) * 129 + grow + 8] = acc[mt][nt][3];
        }
    }
    __syncthreads();
    for (int i = tid; i < 128 * 128; i += 256) {
        int col = i >> 7, row = i & 127;
        pi[(size_t)(bn + col) * TBROWS + (bm + row)] = scS[(size_t)col * 129 + row];
    }
}

// ===================== grouped tensorized recurrent scan =====================
// grid = 52: grp = blk/13 (16 batches), cidx = blk%13 (24 j-cols).
// Per step: z[16, 120] = h[16,300] @ W[300,120], split-bf16 HMMA, 16 warps.
#define OFF_HHI 0
#define OFF_HLO (GB * SHP * 2)                    // 10496
#define OFF_WHI (2 * GB * SHP * 2)                // 20992
#define OFF_WLO (OFF_WHI + 128 * SHP * 2)         // 104960
#define OFF_Z   (OFF_WLO + 128 * SHP * 2)         // 188928
#define SMEM_SCAN_BYTES (OFF_Z + GB * ZP * 4)     // 197696

__global__ void __launch_bounds__(SCANT) lstm_scan(
    const float* __restrict__ Whh, const float* __restrict__ bias,
    const int* __restrict__ lengths, float* __restrict__ ys,
    int reverse, int* __restrict__ flag_layer)
{
    extern __shared__ char smem[];
    const uint32_t sb = smem_u32(smem);
    float* zsm = (float*)(smem + OFF_Z);            // [16][ZP]
    __nv_bfloat16* sWhi = (__nv_bfloat16*)(smem + OFF_WHI);
    __nv_bfloat16* sWlo = (__nv_bfloat16*)(smem + OFF_WLO);

    const int tid = threadIdx.x, warp = tid >> 5, lane = tid & 31;
    const int grp  = blockIdx.x / NCOL;
    const int cidx = blockIdx.x % NCOL;
    const int j0   = cidx * JPC;
    const int wn   = warp * 8;
    int* const flagp = flag_layer + grp * 32;

    // ---- stage W slice [c][k], c = g*24+jl (128 rows, 120 used) ----
    for (int idx = tid; idx < 128 * SHK; idx += SCANT) {
        int c = idx / SHK, k = idx % SHK;
        float v = 0.f;
        int jjj = j0 + (c % JPC);
        if (c < 120 && k < HIDN && jjj < HIDN)
            v = Whh[(size_t)k * G5 + (c / JPC) * HIDN + jjj];
        __nv_bfloat16 h = __float2bfloat16(v);
        sWhi[c * SHP + k] = h;
        sWlo[c * SHP + k] = __float2bfloat16(v - __bfloat162float(h));
    }

    // pointwise owners: tid<384 -> (jl = tid/16, b = tid%16)
    const int b  = tid & 15;
    const int jl = tid >> 4;
    const int bg = grp * GB + b;
    float c_st = 0.f, h_st = 0.f;
    float bi[5] = {0.f, 0.f, 0.f, 0.f, 0.f};
    int len = 0, jj = 0;
    const bool owner = (tid < 384) && (j0 + jl < HIDN);
    if (tid < 384) {
        jj = j0 + jl;
        len = lengths[bg];
        if (owner) {
            #pragma unroll
            for (int g = 0; g < 5; g++) bi[g] = bias[g * HIDN + jj];
        }
    }
    const int Tg = lengths[grp * GB];      // max length in group (sorted desc)
    __syncthreads();

    int p = 0;
    for (int t = 0; t < Tg; t++) {
        // ---- issue h-tile cp.async first (if needed) ----
        if (t > 0) {
            const __nv_bfloat16* hhi = g_hhi + (size_t)(grp * 2 + p) * (GB * SHK);
            const __nv_bfloat16* hlo = g_hlo + (size_t)(grp * 2 + p) * (GB * SHK);
            #pragma unroll
            for (int it = 0; it < 3; it++) {
                int idx = it * SCANT + tid;          // 0..1279
                if (idx < 1280) {
                    int lo_t = idx >= 640;
                    int rc = lo_t ? idx - 640 : idx;
                    int row = rc / 40, ch = rc % 40;
                    const __nv_bfloat16* src = (lo_t ? hlo : hhi) + row * SHK + ch * 8;
                    uint32_t dst = sb + (lo_t ? OFF_HLO : OFF_HHI)
                                 + (uint32_t)(row * SHP + ch * 8) * 2;
                    cp16(dst, src);
                }
            }
            cp_commit();
        }

        // ---- pg prefetch overlaps the cp.async ----
        float pg[6] = {0.f, 0.f, 0.f, 0.f, 0.f, 0.f};
        if (owner) {
            int tr  = reverse ? (len - 1 - t) : t;
            int trc = tr < 0 ? 0 : tr;
            const size_t rb = (size_t)trc * BATCH + bg;
            #pragma unroll
            for (int g = 0; g < 6; g++)
                pg[g] = g_pi[(size_t)(g * HIDN + jj) * TBROWS + rb];
        }

        if (t > 0) {
            cp_wait<0>();
            __syncthreads();

            // ---- HMMA: 10 k-pairs x 3 terms on 3 acc chains ----
            float a0[4] = {0.f, 0.f, 0.f, 0.f};
            float a1[4] = {0.f, 0.f, 0.f, 0.f};
            float a2[4] = {0.f, 0.f, 0.f, 0.f};
            const int arow = lane & 15, akc0 = (lane >> 4) * 8;
            const int bro = wn + (lane & 7), bko = (lane >> 3) * 8;
            #pragma unroll
            for (int kp = 0; kp < 10; kp++) {
                const int k0 = kp * 32;
                uint32_t ah0[4], al0[4], ah1[4], al1[4], rbh[4], rbl[4];
                uint32_t aoff = (uint32_t)(arow * SHP + k0 + akc0) * 2;
                ldsm4(ah0, sb + OFF_HHI + aoff);
                ldsm4(al0, sb + OFF_HLO + aoff);
                ldsm4(ah1, sb + OFF_HHI + aoff + 32);
                ldsm4(al1, sb + OFF_HLO + aoff + 32);
                uint32_t boff = (uint32_t)(bro * SHP + k0 + bko) * 2;
                ldsm4(rbh, sb + OFF_WHI + boff);
                ldsm4(rbl, sb + OFF_WLO + boff);
                mma_bf16(a0, ah0, rbh);
                mma_bf16(a1, ah0, rbl);
                mma_bf16(a2, al0, rbh);
                mma_bf16(a0, ah1, rbh + 2);
                mma_bf16(a1, ah1, rbl + 2);
                mma_bf16(a2, al1, rbh + 2);
            }
            int r0 = lane >> 2, c0 = wn + (lane & 3) * 2;
            zsm[r0 * ZP + c0]           = a0[0] + a1[0] + a2[0];
            zsm[r0 * ZP + c0 + 1]       = a0[1] + a1[1] + a2[1];
            zsm[(r0 + 8) * ZP + c0]     = a0[2] + a1[2] + a2[2];
            zsm[(r0 + 8) * ZP + c0 + 1] = a0[3] + a1[3] + a2[3];
        }
        __syncthreads();

        // ---- pointwise gates ----
        if (owner) {
            float z[5];
            #pragma unroll
            for (int g = 0; g < 5; g++) {
                float zr = (t > 0) ? zsm[b * ZP + g * JPC + jl] : 0.f;
                z[g] = bi[g] + zr + pg[g];
            }
            float ig = 1.f / (1.f + __expf(-z[0]));
            float fg = 1.f / (1.f + __expf(-z[1]));
            float gg = tanhf(z[2]);
            float og = 1.f / (1.f + __expf(-z[3]));
            float rg = 1.f / (1.f + __expf(-z[4]));
            float cn = ig * gg + fg * c_st;
            float lo = og * tanhf(cn);
            float hn = rg * lo + (1.f - rg) * pg[5];

            if (t < len) {
                c_st = cn;
                h_st = hn;
                int tr = reverse ? (len - 1 - t) : t;
                ys[((size_t)tr * BATCH + bg) * HIDN + jj] = hn;
            } else {
                ys[((size_t)t * BATCH + bg) * HIDN + jj] = 0.f;   // padding
            }
            __nv_bfloat16 hh = __float2bfloat16(h_st);
            size_t ho = (size_t)(grp * 2 + (1 - p)) * (GB * SHK) + b * SHK + jj;
            g_hhi[ho] = hh;
            g_hlo[ho] = __float2bfloat16(h_st - __bfloat162float(hh));
        }

        // ---- flag-vector group barrier (no atomic serialization) ----
        __syncthreads();
        if (tid == 0) {
            asm volatile("fence.acq_rel.gpu;" ::: "memory");
            asm volatile("st.relaxed.gpu.global.s32 [%0], %1;"
                         :: "l"(flagp + cidx), "r"(t + 1) : "memory");
        }
        if (tid < 32) {
            int ok;
            do {
                int v = 0x7fffffff;
                if (lane < NCOL)
                    asm volatile("ld.relaxed.gpu.global.s32 %0, [%1];"
                                 : "=r"(v) : "l"(flagp + lane) : "memory");
                ok = __all_sync(0xffffffffu, v >= t + 1);
                if (!ok) __nanosleep(20);
            } while (!ok);
            asm volatile("fence.acq_rel.gpu;" ::: "memory");
        }
        __syncthreads();
        p ^= 1;
    }

    // ---- zero tail region t in [Tg, T_SEQ) for this CTA's slice ----
    for (int idx = tid; idx < (T_SEQ - Tg) * GB * JPC; idx += SCANT) {
        int tt = idx / (GB * JPC);
        int r  = idx % (GB * JPC);
        int bb = r / JPC, jl2 = r % JPC;
        int jjj = j0 + jl2;
        if (jjj < HIDN)
            ys[((size_t)(Tg + tt) * BATCH + (grp * GB + bb)) * HIDN + jjj] = 0.f;
    }
}

// ===================== output transpose =====================
__global__ void __launch_bounds__(256) transpose_out(
    const float* __restrict__ hid7, float* __restrict__ out)
{
    int i = blockIdx.x * 256 + threadIdx.x;
    if (i >= LAYER_SZ) return;
    int h = i % HIDN;
    int r = i / HIDN;
    int b = r % BATCH;
    int t = r / BATCH;
    out[((size_t)b * T_SEQ + t) * HIDN + h] = hid7[i];
}

// ===========================================================================
extern "C" void kernel_launch(void* const* d_in, const int* in_sizes, int n_in,
                              void* d_out, int out_size)
{
    const float* inputs  = (const float*)d_in[0];
    const int*   lengths = (const int*)  d_in[1];
    const float* Wih0    = (const float*)d_in[2];
    const float* Wihr    = (const float*)d_in[3];
    const float* Whh     = (const float*)d_in[4];
    const float* bhh     = (const float*)d_in[5];
    float* out    = (float*)d_out;
    float* hidden = out + OUT_SZ;

    int* flagp = nullptr;
    cudaGetSymbolAddress((void**)&flagp, g_flag);
    float* pip = nullptr;
    cudaGetSymbolAddress((void**)&pip, g_pi);
    __nv_bfloat16 *ahp, *alp, *whp, *wlp;
    cudaGetSymbolAddress((void**)&ahp, g_Ah);
    cudaGetSymbolAddress((void**)&alp, g_Al);
    cudaGetSymbolAddress((void**)&whp, g_Wh);
    cudaGetSymbolAddress((void**)&wlp, g_Wl);

    cudaFuncSetAttribute(hgemm_tc, cudaFuncAttributeMaxDynamicSharedMemorySize,
                         SMEM_GEMM_BYTES);
    cudaFuncSetAttribute(lstm_scan, cudaFuncAttributeMaxDynamicSharedMemorySize,
                         SMEM_SCAN_BYTES);

    cudaMemsetAsync(flagp, 0, NLAYERS * NGRP * 32 * sizeof(int), 0);

    for (int l = 0; l < NLAYERS; l++) {
        const float* A;
        const float* Wih;
        int K, Kpad, nch, a_l0;
        if (l == 0) { A = inputs; Wih = Wih0; K = DIN; Kpad = 256; nch = 8; a_l0 = 1; }
        else {
            A = hidden + (size_t)(l - 1) * LAYER_SZ;
            Wih = Wihr + (size_t)(l - 1) * HIDN * G6;
            K = HIDN; Kpad = 320; nch = 10; a_l0 = 0;
        }

        conv_A<<<TBROWS / 8, 256>>>(A, ahp, alp, K, Kpad, a_l0);
        conv_W<<<dim3(Kpad / 32, NPAD / 32), 256>>>(Wih, whp, wlp, K, Kpad);

        hgemm_tc<<<dim3(NPAD / 128, TBROWS / 128), 256, SMEM_GEMM_BYTES>>>(
            ahp, alp, whp, wlp, pip, Kpad, nch);

        lstm_scan<<<NGRP * NCOL, SCANT, SMEM_SCAN_BYTES>>>(
            Whh + (size_t)l * HIDN * G5,
            bhh + (size_t)l * G5,
            lengths,
            hidden + (size_t)l * LAYER_SZ,
            l & 1,
            flagp + l * NGRP * 32);
    }

    transpose_out<<<(LAYER_SZ + 255) / 256, 256>>>(
        hidden + (size_t)(NLAYERS - 1) * LAYER_SZ, out);
}

// round 14
// speedup vs baseline: 1.5564x; 1.5564x over previous
#include <cuda_runtime.h>
#include <cuda_bf16.h>
#include <cstdint>
#include <cstddef>

#define T_SEQ   256
#define BATCH   64
#define DIN     200
#define HIDN    300
#define NLAYERS 8
#define G5      1500
#define G6      1800
#define NPAD    1920
#define TBROWS  (T_SEQ*BATCH)           // 16384
#define OUT_SZ  (BATCH*T_SEQ*HIDN)
#define LAYER_SZ (T_SEQ*BATCH*HIDN)
#define KPAD_MAX 320

// scan partitioning: 4 batch-groups x 25 column-CTAs (R9 proven)
#define NGRP    4
#define GB      16                      // batches per group
#define NCOL    25                      // CTAs per group
#define JPC     12                      // j-columns per CTA
#define SHK     320                     // padded K for scan MMA (20 k-steps)
#define SHP     328                     // W smem pitch halves (656B)
#define HP2     24                      // h smem pitch halves (48B) - bank-conflict-free

// ---- scratch (device globals; no runtime allocation allowed) ----
__device__ float         g_pi[(size_t)NPAD * TBROWS];   // TRANSPOSED: [col][t*64+b]
__device__ __nv_bfloat16 g_Ah[(size_t)TBROWS * KPAD_MAX];
__device__ __nv_bfloat16 g_Al[(size_t)TBROWS * KPAD_MAX];
__device__ __nv_bfloat16 g_Wh[(size_t)NPAD * KPAD_MAX];
__device__ __nv_bfloat16 g_Wl[(size_t)NPAD * KPAD_MAX];
__device__ __nv_bfloat16 g_hhi[NGRP * 2 * SHK * GB];    // [grp][p][k][b]  (k-major!)
__device__ __nv_bfloat16 g_hlo[NGRP * 2 * SHK * GB];
__device__ int           g_bar[NLAYERS * NGRP * T_SEQ];

// ============================ PTX helpers ============================
__device__ __forceinline__ uint32_t smem_u32(const void* p) {
    uint32_t a;
    asm("{ .reg .u64 t; cvta.to.shared.u64 t, %1; cvt.u32.u64 %0, t; }"
        : "=r"(a) : "l"(p));
    return a;
}
__device__ __forceinline__ void cp16(uint32_t dst, const void* src) {
    asm volatile("cp.async.cg.shared.global [%0], [%1], 16;"
                 :: "r"(dst), "l"(src) : "memory");
}
__device__ __forceinline__ void cp_commit() {
    asm volatile("cp.async.commit_group;" ::: "memory");
}
template <int N>
__device__ __forceinline__ void cp_wait() {
    asm volatile("cp.async.wait_group %0;" :: "n"(N) : "memory");
}
__device__ __forceinline__ void ldsm4(uint32_t* r, uint32_t addr) {
    asm volatile("ldmatrix.sync.aligned.m8n8.x4.shared.b16 {%0,%1,%2,%3}, [%4];"
                 : "=r"(r[0]), "=r"(r[1]), "=r"(r[2]), "=r"(r[3]) : "r"(addr));
}
__device__ __forceinline__ void ldsm4t(uint32_t* r, uint32_t addr) {
    asm volatile("ldmatrix.sync.aligned.m8n8.x4.trans.shared.b16 {%0,%1,%2,%3}, [%4];"
                 : "=r"(r[0]), "=r"(r[1]), "=r"(r[2]), "=r"(r[3]) : "r"(addr));
}
__device__ __forceinline__ void mma_bf16(float* c, const uint32_t* a, const uint32_t* b) {
    asm volatile(
        "mma.sync.aligned.m16n8k16.row.col.f32.bf16.bf16.f32 "
        "{%0,%1,%2,%3}, {%4,%5,%6,%7}, {%8,%9}, {%0,%1,%2,%3};"
        : "+f"(c[0]), "+f"(c[1]), "+f"(c[2]), "+f"(c[3])
        : "r"(a[0]), "r"(a[1]), "r"(a[2]), "r"(a[3]), "r"(b[0]), "r"(b[1]));
}
__device__ __forceinline__ float sigm(float x) {
    return 1.f / (1.f + __expf(-x));
}
__device__ __forceinline__ float tanh_fast(float x) {
    x = fminf(fmaxf(x, -15.f), 15.f);
    float e = __expf(-2.f * x);
    return __fdividef(1.f - e, 1.f + e);
}

// ========================= conversion kernels =========================
__global__ void __launch_bounds__(256) conv_A(
    const float* __restrict__ src, __nv_bfloat16* __restrict__ hi,
    __nv_bfloat16* __restrict__ lo, int K, int Kpad, int l0)
{
    int warp = (blockIdx.x * 256 + threadIdx.x) >> 5;
    int lane = threadIdx.x & 31;
    if (warp >= TBROWS) return;
    const float* s;
    if (l0) { int b = warp & 63, t = warp >> 6; s = src + ((size_t)b * T_SEQ + t) * DIN; }
    else    { s = src + (size_t)warp * HIDN; }
    size_t o = (size_t)warp * Kpad;
    for (int k = lane; k < Kpad; k += 32) {
        float x = (k < K) ? s[k] : 0.f;
        __nv_bfloat16 h = __float2bfloat16(x);
        hi[o + k] = h;
        lo[o + k] = __float2bfloat16(x - __bfloat162float(h));
    }
}

// W [K][1800] -> transposed bf16 hi/lo [NPAD][Kpad]
__global__ void __launch_bounds__(256) conv_W(
    const float* __restrict__ W, __nv_bfloat16* __restrict__ hi,
    __nv_bfloat16* __restrict__ lo, int K, int Kpad)
{
    __shared__ float t[32][33];
    int k0 = blockIdx.x * 32, n0 = blockIdx.y * 32;
    int tx = threadIdx.x & 31, ty = threadIdx.x >> 5;
    #pragma unroll
    for (int i = 0; i < 4; i++) {
        int ky = k0 + ty + i * 8, n = n0 + tx;
        float v = 0.f;
        if (ky < K && n < G6) v = W[(size_t)ky * G6 + n];
        t[ty + i * 8][tx] = v;
    }
    __syncthreads();
    #pragma unroll
    for (int i = 0; i < 4; i++) {
        int n = n0 + ty + i * 8, k = k0 + tx;
        if (n < NPAD && k < Kpad) {
            float v = t[tx][ty + i * 8];
            __nv_bfloat16 h = __float2bfloat16(v);
            hi[(size_t)n * Kpad + k] = h;
            lo[(size_t)n * Kpad + k] = __float2bfloat16(v - __bfloat162float(h));
        }
    }
}

// ===================== split-bf16 HMMA GEMM (input projections) =====================
#define KC 32
#define PITCH 40
#define TILE_H (128 * PITCH)
#define STAGE_H (4 * TILE_H)
#define SMEM_GEMM_BYTES (2 * STAGE_H * 2)

__global__ void __launch_bounds__(256) hgemm_tc(
    const __nv_bfloat16* __restrict__ Ah, const __nv_bfloat16* __restrict__ Al,
    const __nv_bfloat16* __restrict__ Bh, const __nv_bfloat16* __restrict__ Bl,
    float* __restrict__ pi, int Kpad, int nch)
{
    extern __shared__ __nv_bfloat16 sm[];
    const int tid = threadIdx.x, warp = tid >> 5, lane = tid & 31;
    const int bn = blockIdx.x * 128;
    const int bm = blockIdx.y * 128;
    const int wm = (warp >> 2) * 64;
    const int wn = (warp & 3) * 32;
    const uint32_t sb = smem_u32(sm);

    float acc[4][4][4];
    #pragma unroll
    for (int i = 0; i < 4; i++)
        #pragma unroll
        for (int j = 0; j < 4; j++)
            #pragma unroll
            for (int q = 0; q < 4; q++) acc[i][j][q] = 0.f;

    auto load_chunk = [&](int c, int s) {
        const int c0 = c * KC;
        const uint32_t sbase = sb + (uint32_t)s * STAGE_H * 2;
        #pragma unroll
        for (int it = 0; it < 8; it++) {
            int idx = it * 256 + tid;
            int tl  = idx >> 9;
            int r   = (idx >> 2) & 127;
            int seg = idx & 3;
            const __nv_bfloat16* src;
            if      (tl == 0) src = Ah + ((size_t)(bm + r) * Kpad + c0);
            else if (tl == 1) src = Al + ((size_t)(bm + r) * Kpad + c0);
            else if (tl == 2) src = Bh + ((size_t)(bn + r) * Kpad + c0);
            else              src = Bl + ((size_t)(bn + r) * Kpad + c0);
            uint32_t dst = sbase + (uint32_t)(tl * TILE_H + r * PITCH + seg * 8) * 2;
            cp16(dst, src + seg * 8);
        }
    };

    load_chunk(0, 0);
    cp_commit();

    for (int c = 0; c < nch; c++) {
        if (c + 1 < nch) { load_chunk(c + 1, (c + 1) & 1); cp_commit(); cp_wait<1>(); }
        else             { cp_wait<0>(); }
        __syncthreads();

        const uint32_t st = sb + (uint32_t)(c & 1) * STAGE_H * 2;
        const uint32_t sAh = st, sAl = st + TILE_H * 2;
        const uint32_t sBh = st + 2 * TILE_H * 2, sBl = st + 3 * TILE_H * 2;

        #pragma unroll
        for (int ks = 0; ks < 2; ks++) {
            const int k0 = ks * 16;
            uint32_t ah[4][4], al[4][4], bh[4][2], bl[4][2];
            {
                int arow = lane & 15, akc = k0 + (lane >> 4) * 8;
                #pragma unroll
                for (int mt = 0; mt < 4; mt++) {
                    uint32_t off = (uint32_t)((wm + mt * 16 + arow) * PITCH + akc) * 2;
                    ldsm4(ah[mt], sAh + off);
                    ldsm4(al[mt], sAl + off);
                }
            }
            {
                int g = lane >> 3;
                int brow = ((g >= 2) ? 8 : 0) + (lane & 7);
                int bkc  = k0 + ((g & 1) ? 8 : 0);
                #pragma unroll
                for (int h = 0; h < 2; h++) {
                    uint32_t off = (uint32_t)((wn + h * 16 + brow) * PITCH + bkc) * 2;
                    uint32_t r4[4];
                    ldsm4(r4, sBh + off);
                    bh[h * 2 + 0][0] = r4[0]; bh[h * 2 + 0][1] = r4[1];
                    bh[h * 2 + 1][0] = r4[2]; bh[h * 2 + 1][1] = r4[3];
                    ldsm4(r4, sBl + off);
                    bl[h * 2 + 0][0] = r4[0]; bl[h * 2 + 0][1] = r4[1];
                    bl[h * 2 + 1][0] = r4[2]; bl[h * 2 + 1][1] = r4[3];
                }
            }
            #pragma unroll
            for (int mt = 0; mt < 4; mt++)
                #pragma unroll
                for (int nt = 0; nt < 4; nt++)
                    mma_bf16(acc[mt][nt], ah[mt], bh[nt]);
            #pragma unroll
            for (int mt = 0; mt < 4; mt++)
                #pragma unroll
                for (int nt = 0; nt < 4; nt++)
                    mma_bf16(acc[mt][nt], ah[mt], bl[nt]);
            #pragma unroll
            for (int mt = 0; mt < 4; mt++)
                #pragma unroll
                for (int nt = 0; nt < 4; nt++)
                    mma_bf16(acc[mt][nt], al[mt], bh[nt]);
        }
        __syncthreads();
    }

    float* scS = (float*)sm;                 // 128 cols x pitch 129
    #pragma unroll
    for (int mt = 0; mt < 4; mt++) {
        int grow = wm + mt * 16 + (lane >> 2);
        #pragma unroll
        for (int nt = 0; nt < 4; nt++) {
            int gcol = wn + nt * 8 + (lane & 3) * 2;
            scS[(size_t)gcol * 129 + grow]           = acc[mt][nt][0];
            scS[(size_t)(gcol + 1) * 129 + grow]     = acc[mt][nt][1];
            scS[(size_t)gcol * 129 + grow + 8]       = acc[mt][nt][2];
            scS[(size_t)(gcol + 1) * 129 + grow + 8] = acc[mt][nt][3];
        }
    }
    __syncthreads();
    for (int i = tid; i < 128 * 128; i += 256) {
        int col = i >> 7, row = i & 127;
        pi[(size_t)(bn + col) * TBROWS + (bm + row)] = scS[(size_t)col * 129 + row];
    }
}

// ===================== grouped tensorized recurrent scan =====================
// grid = 100: grp = blk/25 (16 batches), cidx = blk%25 (12 j-cols).
// h exchange k-major [k][b]; A-frags via ldmatrix.trans.
#define OFF_HHI 0
#define OFF_HLO (SHK * HP2 * 2)                    // 15360
#define OFF_WHI (2 * SHK * HP2 * 2)                // 30720
#define OFF_WLO (OFF_WHI + 64 * SHP * 2)           // 72704
#define OFF_Z   (OFF_WLO + 64 * SHP * 2)           // 114688
#define SMEM_SCAN_BYTES (OFF_Z + GB * 68 * 4)      // 119040

__global__ void __launch_bounds__(256) lstm_scan(
    const float* __restrict__ Whh, const float* __restrict__ bias,
    const int* __restrict__ lengths, float* __restrict__ ys,
    int reverse, int* __restrict__ bar)
{
    extern __shared__ char smem[];
    const uint32_t sb = smem_u32(smem);
    float* zsm = (float*)(smem + OFF_Z);            // [16][68]
    __nv_bfloat16* sWhi = (__nv_bfloat16*)(smem + OFF_WHI);
    __nv_bfloat16* sWlo = (__nv_bfloat16*)(smem + OFF_WLO);

    const int tid = threadIdx.x, warp = tid >> 5, lane = tid & 31;
    const int grp  = blockIdx.x / NCOL;
    const int cidx = blockIdx.x % NCOL;
    const int j0   = cidx * JPC;
    const int wn   = warp * 8;

    // ---- stage W slice [c][k], c = g*12+jl (64 rows, 60 used) ----
    for (int idx = tid; idx < 64 * SHK; idx += 256) {
        int c = idx / SHK, k = idx % SHK;
        float v = 0.f;
        if (c < 60 && k < HIDN)
            v = Whh[(size_t)k * G5 + (c / JPC) * HIDN + j0 + (c % JPC)];
        __nv_bfloat16 h = __float2bfloat16(v);
        sWhi[c * SHP + k] = h;
        sWlo[c * SHP + k] = __float2bfloat16(v - __bfloat162float(h));
    }

    // pointwise owners: tid<192 -> (jl = tid/16, b = tid%16)
    const int b  = tid & 15;
    const int jl = tid >> 4;
    const int bg = grp * GB + b;
    float c_st = 0.f, h_st = 0.f;
    float bi[5] = {0.f, 0.f, 0.f, 0.f, 0.f};
    int len = 0, jj = 0;
    if (tid < 192) {
        jj = j0 + jl;
        len = lengths[bg];
        #pragma unroll
        for (int g = 0; g < 5; g++) bi[g] = bias[g * HIDN + jj];
    }
    const int Tg = lengths[grp * GB];      // max length in group (sorted desc)
    int* const ctr_base = bar + grp * T_SEQ;
    __syncthreads();

    int p = 0;
    for (int t = 0; t < Tg; t++) {
        // ---- issue h-tile cp.async first: [320][16] k-major, 32B rows ----
        if (t > 0) {
            const __nv_bfloat16* hhi = g_hhi + (size_t)(grp * 2 + p) * (SHK * GB);
            const __nv_bfloat16* hlo = g_hlo + (size_t)(grp * 2 + p) * (SHK * GB);
            #pragma unroll
            for (int it = 0; it < 5; it++) {
                int idx = it * 256 + tid;          // 0..1279
                int lo_t = idx >= 640;
                int rc = lo_t ? idx - 640 : idx;
                int row = rc >> 1, half = rc & 1;
                const __nv_bfloat16* src = (lo_t ? hlo : hhi) + row * GB + half * 8;
                uint32_t dst = sb + (lo_t ? OFF_HLO : OFF_HHI)
                             + (uint32_t)(row * (HP2 * 2) + half * 16);
                cp16(dst, src);
            }
            cp_commit();
        }

        // ---- pg prefetch overlaps the cp.async ----
        float pg[6];
        if (tid < 192) {
            int tr  = reverse ? (len - 1 - t) : t;
            int trc = tr < 0 ? 0 : tr;
            const size_t rb = (size_t)trc * BATCH + bg;
            #pragma unroll
            for (int g = 0; g < 6; g++)
                pg[g] = g_pi[(size_t)(g * HIDN + jj) * TBROWS + rb];
        }

        if (t > 0) {
            cp_wait<0>();
            __syncthreads();

            // ---- HMMA: 10 k-pairs x 3 terms on 3 acc chains ----
            float a0[4] = {0.f, 0.f, 0.f, 0.f};
            float a1[4] = {0.f, 0.f, 0.f, 0.f};
            float a2[4] = {0.f, 0.f, 0.f, 0.f};
            // A-frag (trans) addressing: group = lane>>3
            const int within = lane & 7;
            const int arow   = ((lane >> 3) >= 2) ? 8 : 0;    // +8 k for r2/r3
            const int aboff  = ((lane >> 3) & 1) ? 16 : 0;    // +8 b for r1/r3
            // B-frag addressing (unchanged)
            const int bro = wn + (lane & 7), bko = (lane >> 3) * 8;
            #pragma unroll
            for (int kp = 0; kp < 10; kp++) {
                const int k0 = kp * 32;
                uint32_t ah0[4], al0[4], ah1[4], al1[4], rbh[4], rbl[4];
                uint32_t aoff = (uint32_t)((k0 + arow + within) * (HP2 * 2) + aboff);
                ldsm4t(ah0, sb + OFF_HHI + aoff);
                ldsm4t(al0, sb + OFF_HLO + aoff);
                uint32_t aoff1 = aoff + 16 * (HP2 * 2);
                ldsm4t(ah1, sb + OFF_HHI + aoff1);
                ldsm4t(al1, sb + OFF_HLO + aoff1);
                uint32_t boff = (uint32_t)(bro * SHP + k0 + bko) * 2;
                ldsm4(rbh, sb + OFF_WHI + boff);
                ldsm4(rbl, sb + OFF_WLO + boff);
                mma_bf16(a0, ah0, rbh);
                mma_bf16(a1, ah0, rbl);
                mma_bf16(a2, al0, rbh);
                mma_bf16(a0, ah1, rbh + 2);
                mma_bf16(a1, ah1, rbl + 2);
                mma_bf16(a2, al1, rbh + 2);
            }
            int r0 = lane >> 2, c0 = wn + (lane & 3) * 2;
            zsm[r0 * 68 + c0]           = a0[0] + a1[0] + a2[0];
            zsm[r0 * 68 + c0 + 1]       = a0[1] + a1[1] + a2[1];
            zsm[(r0 + 8) * 68 + c0]     = a0[2] + a1[2] + a2[2];
            zsm[(r0 + 8) * 68 + c0 + 1] = a0[3] + a1[3] + a2[3];
        }
        __syncthreads();

        // ---- pointwise gates ----
        if (tid < 192) {
            float z[5];
            #pragma unroll
            for (int g = 0; g < 5; g++) {
                float zr = (t > 0) ? zsm[b * 68 + g * JPC + jl] : 0.f;
                z[g] = bi[g] + zr + pg[g];
            }
            float ig = sigm(z[0]);
            float fg = sigm(z[1]);
            float gg = tanh_fast(z[2]);
            float og = sigm(z[3]);
            float rg = sigm(z[4]);
            float cn = ig * gg + fg * c_st;
            float lo = og * tanh_fast(cn);
            float hn = rg * lo + (1.f - rg) * pg[5];

            if (t < len) {
                c_st = cn;
                h_st = hn;
                int tr = reverse ? (len - 1 - t) : t;
                ys[((size_t)tr * BATCH + bg) * HIDN + jj] = hn;
            } else {
                ys[((size_t)t * BATCH + bg) * HIDN + jj] = 0.f;   // padding
            }
            // k-major h store: warp's 16 consecutive b -> one 32B run per jl
            __nv_bfloat16 hh = __float2bfloat16(h_st);
            size_t ho = ((size_t)(grp * 2 + (1 - p)) * SHK + jj) * GB + b;
            g_hhi[ho] = hh;
            g_hlo[ho] = __float2bfloat16(h_st - __bfloat162float(hh));
        }

        // ---- group barrier (25 CTAs, per-instruction release/acquire) ----
        __syncthreads();
        if (tid == 0) {
            int* ctr = ctr_base + t;
            asm volatile("red.release.gpu.global.add.s32 [%0], 1;" :: "l"(ctr) : "memory");
            int v;
            do {
                asm volatile("ld.acquire.gpu.global.s32 %0, [%1];" : "=r"(v) : "l"(ctr) : "memory");
                if (v < NCOL) __nanosleep(20);
            } while (v < NCOL);
        }
        __syncthreads();
        p ^= 1;
    }

    // ---- zero tail region t in [Tg, T_SEQ) for this CTA's slice ----
    for (int idx = tid; idx < (T_SEQ - Tg) * GB * JPC; idx += 256) {
        int tt = idx / (GB * JPC);
        int r  = idx % (GB * JPC);
        int bb = r / JPC, jl2 = r % JPC;
        ys[((size_t)(Tg + tt) * BATCH + (grp * GB + bb)) * HIDN + (j0 + jl2)] = 0.f;
    }
}

// ===================== output transpose =====================
__global__ void __launch_bounds__(256) transpose_out(
    const float* __restrict__ hid7, float* __restrict__ out)
{
    int i = blockIdx.x * 256 + threadIdx.x;
    if (i >= LAYER_SZ) return;
    int h = i % HIDN;
    int r = i / HIDN;
    int b = r % BATCH;
    int t = r / BATCH;
    out[((size_t)b * T_SEQ + t) * HIDN + h] = hid7[i];
}

// ===========================================================================
extern "C" void kernel_launch(void* const* d_in, const int* in_sizes, int n_in,
                              void* d_out, int out_size)
{
    const float* inputs  = (const float*)d_in[0];
    const int*   lengths = (const int*)  d_in[1];
    const float* Wih0    = (const float*)d_in[2];
    const float* Wihr    = (const float*)d_in[3];
    const float* Whh     = (const float*)d_in[4];
    const float* bhh     = (const float*)d_in[5];
    float* out    = (float*)d_out;
    float* hidden = out + OUT_SZ;

    int* barp = nullptr;
    cudaGetSymbolAddress((void**)&barp, g_bar);
    float* pip = nullptr;
    cudaGetSymbolAddress((void**)&pip, g_pi);
    __nv_bfloat16 *ahp, *alp, *whp, *wlp;
    cudaGetSymbolAddress((void**)&ahp, g_Ah);
    cudaGetSymbolAddress((void**)&alp, g_Al);
    cudaGetSymbolAddress((void**)&whp, g_Wh);
    cudaGetSymbolAddress((void**)&wlp, g_Wl);

    cudaFuncSetAttribute(hgemm_tc, cudaFuncAttributeMaxDynamicSharedMemorySize,
                         SMEM_GEMM_BYTES);
    cudaFuncSetAttribute(lstm_scan, cudaFuncAttributeMaxDynamicSharedMemorySize,
                         SMEM_SCAN_BYTES);

    cudaMemsetAsync(barp, 0, NLAYERS * NGRP * T_SEQ * sizeof(int), 0);

    for (int l = 0; l < NLAYERS; l++) {
        const float* A;
        const float* Wih;
        int K, Kpad, nch, a_l0;
        if (l == 0) { A = inputs; Wih = Wih0; K = DIN; Kpad = 256; nch = 8; a_l0 = 1; }
        else {
            A = hidden + (size_t)(l - 1) * LAYER_SZ;
            Wih = Wihr + (size_t)(l - 1) * HIDN * G6;
            K = HIDN; Kpad = 320; nch = 10; a_l0 = 0;
        }

        conv_A<<<TBROWS / 8, 256>>>(A, ahp, alp, K, Kpad, a_l0);
        conv_W<<<dim3(Kpad / 32, NPAD / 32), 256>>>(Wih, whp, wlp, K, Kpad);

        hgemm_tc<<<dim3(NPAD / 128, TBROWS / 128), 256, SMEM_GEMM_BYTES>>>(
            ahp, alp, whp, wlp, pip, Kpad, nch);

        lstm_scan<<<NGRP * NCOL, 256, SMEM_SCAN_BYTES>>>(
            Whh + (size_t)l * HIDN * G5,
            bhh + (size_t)l * G5,
            lengths,
            hidden + (size_t)l * LAYER_SZ,
            l & 1,
            barp + l * NGRP * T_SEQ);
    }

    transpose_out<<<(LAYER_SZ + 255) / 256, 256>>>(
        hidden + (size_t)(NLAYERS - 1) * LAYER_SZ, out);
}